// round 2
// baseline (speedup 1.0000x reference)
#include <cuda_runtime.h>
#include <math.h>

#define BATCH   2
#define SEQ     2048
#define DMODEL  2048
#define NHEADS  16
#define DHEAD   128
#define NTOK    (BATCH * SEQ)      // 4096

// ---------------- scratch (device globals; no allocation allowed) ----------
__device__ float g_q[(size_t)BATCH * NHEADS * SEQ * DHEAD];  // [b][h][s][d]
__device__ float g_k[(size_t)BATCH * NHEADS * SEQ * DHEAD];
__device__ float g_v[(size_t)BATCH * NHEADS * SEQ * DHEAD];
__device__ float g_z[(size_t)BATCH * SEQ * NHEADS * DHEAD];  // [b][s][h][d] == [4096][2048]

// ---------------------------------------------------------------------------
// Fused QKV projection: for which in {Q,K,V}:
//   out[b,h,s,d] = sum_m resid[b,s,m] * W[h,m,d] + bias[h,d]
// GEMM: A=[4096 x 2048] (resid), B per head = W + h*2048*128 -> [2048 x 128] rm
// grid: (32 m-tiles, 16 heads, 3 which), block 256, 128x128 tile, 8x8/thread
// ---------------------------------------------------------------------------
__global__ __launch_bounds__(256) void qkv_gemm(
    const float* __restrict__ A,
    const float* __restrict__ WQ, const float* __restrict__ WK, const float* __restrict__ WV,
    const float* __restrict__ bQ, const float* __restrict__ bK, const float* __restrict__ bV)
{
    __shared__ float As[16][128];   // A tile transposed: As[k][row]
    __shared__ float Bs[16][128];

    const int tid = threadIdx.x;
    const int tx = tid & 15;        // n dir
    const int ty = tid >> 4;        // m dir
    const int i0 = blockIdx.x * 128;
    const int h  = blockIdx.y;
    const int which = blockIdx.z;

    const float* W    = (which == 0) ? WQ : (which == 1) ? WK : WV;
    const float* bias = (which == 0) ? bQ : (which == 1) ? bK : bV;
    float* outbuf     = (which == 0) ? g_q : (which == 1) ? g_k : g_v;

    const float* Wh = W + (size_t)h * DMODEL * DHEAD;   // [2048 x 128] row-major

    float acc[8][8];
    #pragma unroll
    for (int r = 0; r < 8; r++)
        #pragma unroll
        for (int c = 0; c < 8; c++) acc[r][c] = 0.0f;

    for (int k0 = 0; k0 < DMODEL; k0 += 16) {
        // A tile 128x16 -> As (transposed)
        #pragma unroll
        for (int it = 0; it < 2; it++) {
            int idx = tid + it * 256;            // 0..511
            int ar  = idx >> 2;                  // 0..127
            int ac  = (idx & 3) * 4;             // 0,4,8,12
            float4 v = *reinterpret_cast<const float4*>(
                A + (size_t)(i0 + ar) * DMODEL + k0 + ac);
            As[ac + 0][ar] = v.x; As[ac + 1][ar] = v.y;
            As[ac + 2][ar] = v.z; As[ac + 3][ar] = v.w;
        }
        // B tile 16x128
        #pragma unroll
        for (int it = 0; it < 2; it++) {
            int idx = tid + it * 256;
            int br  = idx >> 5;                  // 0..15
            int bc  = (idx & 31) * 4;            // 0..124
            *reinterpret_cast<float4*>(&Bs[br][bc]) =
                *reinterpret_cast<const float4*>(Wh + (size_t)(k0 + br) * DHEAD + bc);
        }
        __syncthreads();

        #pragma unroll
        for (int kk = 0; kk < 16; kk++) {
            float ra[8], rb[8];
            *reinterpret_cast<float4*>(&ra[0]) = *reinterpret_cast<float4*>(&As[kk][ty * 8]);
            *reinterpret_cast<float4*>(&ra[4]) = *reinterpret_cast<float4*>(&As[kk][ty * 8 + 4]);
            *reinterpret_cast<float4*>(&rb[0]) = *reinterpret_cast<float4*>(&Bs[kk][tx * 8]);
            *reinterpret_cast<float4*>(&rb[4]) = *reinterpret_cast<float4*>(&Bs[kk][tx * 8 + 4]);
            #pragma unroll
            for (int r = 0; r < 8; r++)
                #pragma unroll
                for (int c = 0; c < 8; c++)
                    acc[r][c] += ra[r] * rb[c];
        }
        __syncthreads();
    }

    // epilogue: write to [b][h][s][d]
    #pragma unroll
    for (int r = 0; r < 8; r++) {
        int i = i0 + ty * 8 + r;                 // token index
        int b = i >> 11;
        int s = i & 2047;
        float* orow = outbuf + (((size_t)b * NHEADS + h) * SEQ + s) * DHEAD + tx * 8;
        #pragma unroll
        for (int c = 0; c < 8; c++)
            orow[c] = acc[r][c] + bias[h * DHEAD + tx * 8 + c];
    }
}

// ---------------------------------------------------------------------------
// Output projection: out[i, jg] = sum_k z[i,k] * WO[k, jg] + bO[jg]
// z is [4096 x 2048] (b,s major; h*128+d cols). WO [16,128,2048] == [2048 x 2048] rm.
// ---------------------------------------------------------------------------
__global__ __launch_bounds__(256) void o_gemm(
    const float* __restrict__ WO, const float* __restrict__ bO, float* __restrict__ out)
{
    __shared__ float As[16][128];
    __shared__ float Bs[16][128];

    const int tid = threadIdx.x;
    const int tx = tid & 15;
    const int ty = tid >> 4;
    const int i0 = blockIdx.x * 128;
    const int j0 = blockIdx.y * 128;
    const float* A = g_z;

    float acc[8][8];
    #pragma unroll
    for (int r = 0; r < 8; r++)
        #pragma unroll
        for (int c = 0; c < 8; c++) acc[r][c] = 0.0f;

    for (int k0 = 0; k0 < DMODEL; k0 += 16) {
        #pragma unroll
        for (int it = 0; it < 2; it++) {
            int idx = tid + it * 256;
            int ar  = idx >> 2;
            int ac  = (idx & 3) * 4;
            float4 v = *reinterpret_cast<const float4*>(
                A + (size_t)(i0 + ar) * DMODEL + k0 + ac);
            As[ac + 0][ar] = v.x; As[ac + 1][ar] = v.y;
            As[ac + 2][ar] = v.z; As[ac + 3][ar] = v.w;
        }
        #pragma unroll
        for (int it = 0; it < 2; it++) {
            int idx = tid + it * 256;
            int br  = idx >> 5;
            int bc  = (idx & 31) * 4;
            *reinterpret_cast<float4*>(&Bs[br][bc]) =
                *reinterpret_cast<const float4*>(WO + (size_t)(k0 + br) * DMODEL + j0 + bc);
        }
        __syncthreads();

        #pragma unroll
        for (int kk = 0; kk < 16; kk++) {
            float ra[8], rb[8];
            *reinterpret_cast<float4*>(&ra[0]) = *reinterpret_cast<float4*>(&As[kk][ty * 8]);
            *reinterpret_cast<float4*>(&ra[4]) = *reinterpret_cast<float4*>(&As[kk][ty * 8 + 4]);
            *reinterpret_cast<float4*>(&rb[0]) = *reinterpret_cast<float4*>(&Bs[kk][tx * 8]);
            *reinterpret_cast<float4*>(&rb[4]) = *reinterpret_cast<float4*>(&Bs[kk][tx * 8 + 4]);
            #pragma unroll
            for (int r = 0; r < 8; r++)
                #pragma unroll
                for (int c = 0; c < 8; c++)
                    acc[r][c] += ra[r] * rb[c];
        }
        __syncthreads();
    }

    #pragma unroll
    for (int r = 0; r < 8; r++) {
        int i = i0 + ty * 8 + r;
        float* orow = out + (size_t)i * DMODEL + j0 + tx * 8;
        #pragma unroll
        for (int c = 0; c < 8; c++)
            orow[c] = acc[r][c] + bO[j0 + tx * 8 + c];
    }
}

// ---------------------------------------------------------------------------
// Causal flash attention (fp32, online softmax).
// grid (32 q-tiles, 16 heads, 2 batch), 256 threads.
// BQ=64 q rows per block, stream K/V in 64-row tiles. No score materialization.
// thread (tx,ty) = (k-dir 16, q-dir 16): 4x4 scores, 4x8 output accum.
// ---------------------------------------------------------------------------
#define BQ   64
#define BKT  64
#define QPAD 132   // 128 + 4 pad (keeps float4 alignment: 132*4 % 16 == 0)
#define PPAD 68

extern __shared__ float attn_smem[];

__global__ __launch_bounds__(256) void attn_kernel()
{
    float* Qs = attn_smem;                 // [64][132]
    float* Ks = Qs + BQ  * QPAD;           // [64][132]
    float* Vs = Ks + BKT * QPAD;           // [64][132]
    float* Ps = Vs + BKT * QPAD;           // [64][68]

    const int tid = threadIdx.x;
    const int tx = tid & 15;
    const int ty = tid >> 4;
    const int q0 = blockIdx.x * BQ;
    const int h  = blockIdx.y;
    const int b  = blockIdx.z;

    const float* Qg = g_q + (((size_t)b * NHEADS + h) * SEQ + q0) * DHEAD;
    const float* Kg = g_k + ((size_t)b * NHEADS + h) * SEQ * DHEAD;
    const float* Vg = g_v + ((size_t)b * NHEADS + h) * SEQ * DHEAD;

    // load Q tile (64 x 128)
    for (int idx = tid; idx < BQ * 32; idx += 256) {
        int r = idx >> 5;
        int c = (idx & 31) * 4;
        *reinterpret_cast<float4*>(&Qs[r * QPAD + c]) =
            *reinterpret_cast<const float4*>(Qg + (size_t)r * DHEAD + c);
    }

    float m[4], l[4], o[4][8];
    #pragma unroll
    for (int qi = 0; qi < 4; qi++) {
        m[qi] = -INFINITY; l[qi] = 0.0f;
        #pragma unroll
        for (int dj = 0; dj < 8; dj++) o[qi][dj] = 0.0f;
    }

    const float sc_scale = 0.08838834764831843f;   // 1/sqrt(128)
    const int kend = q0 + BQ;

    for (int k0 = 0; k0 < kend; k0 += BKT) {
        __syncthreads();   // previous tile's Ks/Vs/Ps reads done
        for (int idx = tid; idx < BKT * 32; idx += 256) {
            int r = idx >> 5;
            int c = (idx & 31) * 4;
            *reinterpret_cast<float4*>(&Ks[r * QPAD + c]) =
                *reinterpret_cast<const float4*>(Kg + (size_t)(k0 + r) * DHEAD + c);
            *reinterpret_cast<float4*>(&Vs[r * QPAD + c]) =
                *reinterpret_cast<const float4*>(Vg + (size_t)(k0 + r) * DHEAD + c);
        }
        __syncthreads();

        // S = Q K^T (4x4 per thread)
        float sc[4][4];
        #pragma unroll
        for (int qi = 0; qi < 4; qi++)
            #pragma unroll
            for (int ki = 0; ki < 4; ki++) sc[qi][ki] = 0.0f;

        for (int d = 0; d < DHEAD; d += 4) {
            float4 qv[4], kv[4];
            #pragma unroll
            for (int qi = 0; qi < 4; qi++)
                qv[qi] = *reinterpret_cast<float4*>(&Qs[(ty * 4 + qi) * QPAD + d]);
            #pragma unroll
            for (int ki = 0; ki < 4; ki++)
                kv[ki] = *reinterpret_cast<float4*>(&Ks[(tx * 4 + ki) * QPAD + d]);
            #pragma unroll
            for (int qi = 0; qi < 4; qi++)
                #pragma unroll
                for (int ki = 0; ki < 4; ki++) {
                    sc[qi][ki] += qv[qi].x * kv[ki].x;
                    sc[qi][ki] += qv[qi].y * kv[ki].y;
                    sc[qi][ki] += qv[qi].z * kv[ki].z;
                    sc[qi][ki] += qv[qi].w * kv[ki].w;
                }
        }

        // online softmax per q row
        #pragma unroll
        for (int qi = 0; qi < 4; qi++) {
            const int qg = q0 + ty * 4 + qi;
            float tmax = -INFINITY;
            #pragma unroll
            for (int ki = 0; ki < 4; ki++) {
                float s = sc[qi][ki] * sc_scale;
                int kg = k0 + tx * 4 + ki;
                if (kg > qg) s = -INFINITY;       // causal mask
                sc[qi][ki] = s;
                tmax = fmaxf(tmax, s);
            }
            #pragma unroll
            for (int off = 8; off > 0; off >>= 1)
                tmax = fmaxf(tmax, __shfl_xor_sync(0xffffffffu, tmax, off));

            float mnew = fmaxf(m[qi], tmax);
            float corr = __expf(m[qi] - mnew);    // exp(-inf)=0 on first tile

            float rsum = 0.0f;
            #pragma unroll
            for (int ki = 0; ki < 4; ki++) {
                float p = __expf(sc[qi][ki] - mnew);
                sc[qi][ki] = p;
                rsum += p;
            }
            #pragma unroll
            for (int off = 8; off > 0; off >>= 1)
                rsum += __shfl_xor_sync(0xffffffffu, rsum, off);

            l[qi] = l[qi] * corr + rsum;
            m[qi] = mnew;
            #pragma unroll
            for (int dj = 0; dj < 8; dj++) o[qi][dj] *= corr;

            #pragma unroll
            for (int ki = 0; ki < 4; ki++)
                Ps[(ty * 4 + qi) * PPAD + tx * 4 + ki] = sc[qi][ki];
        }
        __syncthreads();

        // O += P @ V   (thread: 4 q rows x 8 d cols, d cols = tx*8..tx*8+7)
        for (int kk = 0; kk < BKT; kk++) {
            float4 v0 = *reinterpret_cast<float4*>(&Vs[kk * QPAD + tx * 8]);
            float4 v1 = *reinterpret_cast<float4*>(&Vs[kk * QPAD + tx * 8 + 4]);
            #pragma unroll
            for (int qi = 0; qi < 4; qi++) {
                float p = Ps[(ty * 4 + qi) * PPAD + kk];
                o[qi][0] += p * v0.x; o[qi][1] += p * v0.y;
                o[qi][2] += p * v0.z; o[qi][3] += p * v0.w;
                o[qi][4] += p * v1.x; o[qi][5] += p * v1.y;
                o[qi][6] += p * v1.z; o[qi][7] += p * v1.w;
            }
        }
    }

    // normalize + write z[b][s][h][d]
    #pragma unroll
    for (int qi = 0; qi < 4; qi++) {
        float inv = 1.0f / l[qi];
        int s = q0 + ty * 4 + qi;
        float* zp = g_z + (((size_t)b * SEQ + s) * NHEADS + h) * DHEAD + tx * 8;
        #pragma unroll
        for (int dj = 0; dj < 8; dj++) zp[dj] = o[qi][dj] * inv;
    }
}

// ---------------------------------------------------------------------------
extern "C" void kernel_launch(void* const* d_in, const int* in_sizes, int n_in,
                              void* d_out, int out_size)
{
    (void)in_sizes; (void)n_in; (void)out_size;
    const float* residual = (const float*)d_in[0];
    // d_in[1] = x, unused (use_split_qkv_input=False)
    const float* WQ = (const float*)d_in[2];
    const float* WK = (const float*)d_in[3];
    const float* WV = (const float*)d_in[4];
    const float* WO = (const float*)d_in[5];
    const float* bQ = (const float*)d_in[6];
    const float* bK = (const float*)d_in[7];
    const float* bV = (const float*)d_in[8];
    const float* bO = (const float*)d_in[9];
    float* out = (float*)d_out;

    // output tuple element 0: residual pass-through
    cudaMemcpyAsync(out, residual, (size_t)BATCH * SEQ * DMODEL * sizeof(float),
                    cudaMemcpyDeviceToDevice);

    // 1) fused QKV projection
    dim3 g1(NTOK / 128, NHEADS, 3);
    qkv_gemm<<<g1, 256>>>(residual, WQ, WK, WV, bQ, bK, bV);

    // 2) causal flash attention
    const int smem_bytes = (3 * BKT * QPAD + BQ * PPAD) * (int)sizeof(float); // 118784
    cudaFuncSetAttribute(attn_kernel, cudaFuncAttributeMaxDynamicSharedMemorySize,
                         smem_bytes);
    dim3 g2(SEQ / BQ, NHEADS, BATCH);
    attn_kernel<<<g2, 256, smem_bytes>>>();

    // 3) output projection into tuple element 1
    dim3 g3(NTOK / 128, DMODEL / 128);
    o_gemm<<<g3, 256>>>(WO, bO, out + (size_t)BATCH * SEQ * DMODEL);
}

// round 4
// speedup vs baseline: 1.6147x; 1.6147x over previous
#include <cuda_runtime.h>
#include <cuda_bf16.h>
#include <math.h>
#include <stdint.h>

#define BATCH   2
#define SEQ     2048
#define DMODEL  2048
#define NHEADS  16
#define DHEAD   128
#define NTOK    (BATCH * SEQ)      // 4096

// ---------------- scratch (device globals; no allocation allowed) ----------
__device__ float g_q[(size_t)BATCH * NHEADS * SEQ * DHEAD];  // [b][h][s][d]
__device__ float g_k[(size_t)BATCH * NHEADS * SEQ * DHEAD];
__device__ float g_v[(size_t)BATCH * NHEADS * SEQ * DHEAD];
__device__ float g_z[(size_t)BATCH * SEQ * NHEADS * DHEAD];  // [b][s][h][d] == [4096][2048]

// ========================= mma.sync helpers ================================
__device__ __forceinline__ void ldsm_x4(uint32_t r[4], uint32_t addr) {
    asm volatile("ldmatrix.sync.aligned.m8n8.x4.shared.b16 {%0,%1,%2,%3}, [%4];"
                 : "=r"(r[0]), "=r"(r[1]), "=r"(r[2]), "=r"(r[3]) : "r"(addr));
}
__device__ __forceinline__ void ldsm_x4_t(uint32_t r[4], uint32_t addr) {
    asm volatile("ldmatrix.sync.aligned.m8n8.x4.trans.shared.b16 {%0,%1,%2,%3}, [%4];"
                 : "=r"(r[0]), "=r"(r[1]), "=r"(r[2]), "=r"(r[3]) : "r"(addr));
}
__device__ __forceinline__ void mma_bf16(float c[4], const uint32_t a[4],
                                         uint32_t b0, uint32_t b1) {
    asm volatile("mma.sync.aligned.m16n8k16.row.col.f32.bf16.bf16.f32 "
                 "{%0,%1,%2,%3}, {%4,%5,%6,%7}, {%8,%9}, {%0,%1,%2,%3};"
                 : "+f"(c[0]), "+f"(c[1]), "+f"(c[2]), "+f"(c[3])
                 : "r"(a[0]), "r"(a[1]), "r"(a[2]), "r"(a[3]), "r"(b0), "r"(b1));
}
__device__ __forceinline__ uint32_t smem_to_u32(const void* p) {
    uint32_t a;
    asm("{ .reg .u64 t; cvta.to.shared.u64 t, %1; cvt.u32.u64 %0, t; }"
        : "=r"(a) : "l"(p));
    return a;
}
__device__ __forceinline__ uint32_t pack2(__nv_bfloat16 lo, __nv_bfloat16 hi) {
    return (uint32_t)__bfloat16_as_ushort(lo) | ((uint32_t)__bfloat16_as_ushort(hi) << 16);
}

// ===================== split-bf16 GEMM mainloop ============================
// D[128,128] = A[128,2048] @ B[2048,128], B row-major [k][n].
// 3-pass: Ahi*Bhi + Ahi*Blo + Alo*Bhi, fp32 accumulate in registers.
// smem: Ahi [128][64]bf16 @0, Alo @16K, Bhi [64][128]bf16 @32K, Blo @48K.
#define KT      64
#define SM_AHI  0
#define SM_ALO  16384
#define SM_BHI  32768
#define SM_BLO  49152
#define SM_GEMM 65536

__device__ __forceinline__ void gemm_mainloop(
    const float* __restrict__ A, int lda,
    const float* __restrict__ B, int ldb,
    char* smem, float acc[4][4][4])
{
    const int tid  = threadIdx.x;
    const int lane = tid & 31;
    const int wid  = tid >> 5;
    const int wm   = (wid >> 2) * 64;     // warp m offset (0/64)
    const int wn   = (wid & 3) * 32;      // warp n offset (0/32/64/96)
    const uint32_t sb = smem_to_u32(smem);

    for (int k0 = 0; k0 < DMODEL; k0 += KT) {
        __syncthreads();
        // --- A tile [128 x 64] fp32 -> hi/lo bf16 (swizzled) ---
        #pragma unroll
        for (int it = 0; it < 8; it++) {
            int idx = tid + it * 256;             // 0..2047
            int m  = idx >> 4;                    // 0..127
            int kq = (idx & 15) * 4;              // 0..60
            float4 v = *reinterpret_cast<const float4*>(A + (size_t)m * lda + k0 + kq);
            __nv_bfloat16 hx = __float2bfloat16(v.x), hy = __float2bfloat16(v.y);
            __nv_bfloat16 hz = __float2bfloat16(v.z), hw = __float2bfloat16(v.w);
            __nv_bfloat16 lx = __float2bfloat16(v.x - __bfloat162float(hx));
            __nv_bfloat16 ly = __float2bfloat16(v.y - __bfloat162float(hy));
            __nv_bfloat16 lz = __float2bfloat16(v.z - __bfloat162float(hz));
            __nv_bfloat16 lw = __float2bfloat16(v.w - __bfloat162float(hw));
            uint32_t off = (uint32_t)(m * 128 + (((kq >> 3) ^ (m & 7)) << 4) + (kq & 7) * 2);
            *reinterpret_cast<uint2*>(smem + SM_AHI + off) = make_uint2(pack2(hx, hy), pack2(hz, hw));
            *reinterpret_cast<uint2*>(smem + SM_ALO + off) = make_uint2(pack2(lx, ly), pack2(lz, lw));
        }
        // --- B tile [64 x 128] fp32 -> hi/lo bf16 (swizzled) ---
        #pragma unroll
        for (int it = 0; it < 8; it++) {
            int idx = tid + it * 256;
            int k  = idx >> 5;                    // 0..63
            int nq = (idx & 31) * 4;              // 0..124
            float4 v = *reinterpret_cast<const float4*>(B + (size_t)(k0 + k) * ldb + nq);
            __nv_bfloat16 hx = __float2bfloat16(v.x), hy = __float2bfloat16(v.y);
            __nv_bfloat16 hz = __float2bfloat16(v.z), hw = __float2bfloat16(v.w);
            __nv_bfloat16 lx = __float2bfloat16(v.x - __bfloat162float(hx));
            __nv_bfloat16 ly = __float2bfloat16(v.y - __bfloat162float(hy));
            __nv_bfloat16 lz = __float2bfloat16(v.z - __bfloat162float(hz));
            __nv_bfloat16 lw = __float2bfloat16(v.w - __bfloat162float(hw));
            uint32_t off = (uint32_t)(k * 256 + (((nq >> 3) ^ (k & 7)) << 4) + (nq & 7) * 2);
            *reinterpret_cast<uint2*>(smem + SM_BHI + off) = make_uint2(pack2(hx, hy), pack2(hz, hw));
            *reinterpret_cast<uint2*>(smem + SM_BLO + off) = make_uint2(pack2(lx, ly), pack2(lz, lw));
        }
        __syncthreads();

        // --- MMA over 4 k16 steps ---
        #pragma unroll
        for (int k16 = 0; k16 < 4; k16++) {
            // B fragments: 2x ldmatrix.x4.trans covers 4 n-frags (hi + lo)
            uint32_t bh[4][2], bl[4][2];
            #pragma unroll
            for (int nf = 0; nf < 2; nf++) {
                int kk = k16 * 16 + (lane & 15);
                int nn = wn + nf * 16 + ((lane >> 4) << 3);
                uint32_t off = (uint32_t)(kk * 256 + (((nn >> 3) ^ (kk & 7)) << 4));
                uint32_t r[4];
                ldsm_x4_t(r, sb + SM_BHI + off);
                bh[nf * 2][0] = r[0]; bh[nf * 2][1] = r[1];
                bh[nf * 2 + 1][0] = r[2]; bh[nf * 2 + 1][1] = r[3];
                ldsm_x4_t(r, sb + SM_BLO + off);
                bl[nf * 2][0] = r[0]; bl[nf * 2][1] = r[1];
                bl[nf * 2 + 1][0] = r[2]; bl[nf * 2 + 1][1] = r[3];
            }
            #pragma unroll
            for (int mi = 0; mi < 4; mi++) {
                int mm = wm + mi * 16 + (lane & 15);
                int kk = k16 * 16 + ((lane >> 4) << 3);
                uint32_t off = (uint32_t)(mm * 128 + (((kk >> 3) ^ (mm & 7)) << 4));
                uint32_t ah[4], al[4];
                ldsm_x4(ah, sb + SM_AHI + off);
                ldsm_x4(al, sb + SM_ALO + off);
                #pragma unroll
                for (int ni = 0; ni < 4; ni++) {
                    mma_bf16(acc[mi][ni], ah, bh[ni][0], bh[ni][1]);
                    mma_bf16(acc[mi][ni], ah, bl[ni][0], bl[ni][1]);
                    mma_bf16(acc[mi][ni], al, bh[ni][0], bh[ni][1]);
                }
            }
        }
    }
}

// ----------------------- QKV projection ------------------------------------
__global__ __launch_bounds__(256, 2) void qkv_tc(
    const float* __restrict__ resid,
    const float* __restrict__ WQ, const float* __restrict__ WK,
    const float* __restrict__ WV,
    const float* __restrict__ bQ, const float* __restrict__ bK,
    const float* __restrict__ bV)
{
    extern __shared__ char smem[];
    const int i0 = blockIdx.x * 128;
    const int h  = blockIdx.y;
    const int which = blockIdx.z;

    const float* W    = (which == 0) ? WQ : (which == 1) ? WK : WV;
    const float* bias = (which == 0) ? bQ : (which == 1) ? bK : bV;
    float* outbuf     = (which == 0) ? g_q : (which == 1) ? g_k : g_v;

    float acc[4][4][4];
    #pragma unroll
    for (int mi = 0; mi < 4; mi++)
        #pragma unroll
        for (int ni = 0; ni < 4; ni++)
            #pragma unroll
            for (int j = 0; j < 4; j++) acc[mi][ni][j] = 0.0f;

    gemm_mainloop(resid + (size_t)i0 * DMODEL, DMODEL,
                  W + (size_t)h * DMODEL * DHEAD, DHEAD, smem, acc);

    // epilogue: c frag rows l/4 & l/4+8, cols (l%4)*2,+1
    const int lane = threadIdx.x & 31;
    const int wid  = threadIdx.x >> 5;
    const int wm   = (wid >> 2) * 64;
    const int wn   = (wid & 3) * 32;
    #pragma unroll
    for (int mi = 0; mi < 4; mi++) {
        #pragma unroll
        for (int ni = 0; ni < 4; ni++) {
            int col = wn + ni * 8 + (lane & 3) * 2;
            float b0 = bias[h * DHEAD + col];
            float b1 = bias[h * DHEAD + col + 1];
            #pragma unroll
            for (int half = 0; half < 2; half++) {
                int i = i0 + wm + mi * 16 + (lane >> 2) + half * 8;   // token index
                int bb = i >> 11, s = i & 2047;
                float* op = outbuf + (((size_t)bb * NHEADS + h) * SEQ + s) * DHEAD + col;
                float2 v = make_float2(acc[mi][ni][half * 2] + b0,
                                       acc[mi][ni][half * 2 + 1] + b1);
                *reinterpret_cast<float2*>(op) = v;
            }
        }
    }
}

// ----------------------- Output projection ---------------------------------
__global__ __launch_bounds__(256, 2) void o_tc(
    const float* __restrict__ WO, const float* __restrict__ bO,
    float* __restrict__ out)
{
    extern __shared__ char smem[];
    const int i0 = blockIdx.x * 128;
    const int j0 = blockIdx.y * 128;

    float acc[4][4][4];
    #pragma unroll
    for (int mi = 0; mi < 4; mi++)
        #pragma unroll
        for (int ni = 0; ni < 4; ni++)
            #pragma unroll
            for (int j = 0; j < 4; j++) acc[mi][ni][j] = 0.0f;

    gemm_mainloop(g_z + (size_t)i0 * DMODEL, DMODEL, WO + j0, DMODEL, smem, acc);

    const int lane = threadIdx.x & 31;
    const int wid  = threadIdx.x >> 5;
    const int wm   = (wid >> 2) * 64;
    const int wn   = (wid & 3) * 32;
    #pragma unroll
    for (int mi = 0; mi < 4; mi++) {
        #pragma unroll
        for (int ni = 0; ni < 4; ni++) {
            int col = j0 + wn + ni * 8 + (lane & 3) * 2;
            float b0 = bO[col], b1 = bO[col + 1];
            #pragma unroll
            for (int half = 0; half < 2; half++) {
                int i = i0 + wm + mi * 16 + (lane >> 2) + half * 8;
                float2 v = make_float2(acc[mi][ni][half * 2] + b0,
                                       acc[mi][ni][half * 2 + 1] + b1);
                *reinterpret_cast<float2*>(out + (size_t)i * DMODEL + col) = v;
            }
        }
    }
}

// ---------------------------------------------------------------------------
// Causal flash attention (fp32, online softmax) — unchanged (verified R1).
// ---------------------------------------------------------------------------
#define BQ   64
#define BKT  64
#define QPAD 132
#define PPAD 68

extern __shared__ float attn_smem[];

__global__ __launch_bounds__(256) void attn_kernel()
{
    float* Qs = attn_smem;
    float* Ks = Qs + BQ  * QPAD;
    float* Vs = Ks + BKT * QPAD;
    float* Ps = Vs + BKT * QPAD;

    const int tid = threadIdx.x;
    const int tx = tid & 15;
    const int ty = tid >> 4;
    const int q0 = blockIdx.x * BQ;
    const int h  = blockIdx.y;
    const int b  = blockIdx.z;

    const float* Qg = g_q + (((size_t)b * NHEADS + h) * SEQ + q0) * DHEAD;
    const float* Kg = g_k + ((size_t)b * NHEADS + h) * SEQ * DHEAD;
    const float* Vg = g_v + ((size_t)b * NHEADS + h) * SEQ * DHEAD;

    for (int idx = tid; idx < BQ * 32; idx += 256) {
        int r = idx >> 5;
        int c = (idx & 31) * 4;
        *reinterpret_cast<float4*>(&Qs[r * QPAD + c]) =
            *reinterpret_cast<const float4*>(Qg + (size_t)r * DHEAD + c);
    }

    float m[4], l[4], o[4][8];
    #pragma unroll
    for (int qi = 0; qi < 4; qi++) {
        m[qi] = -INFINITY; l[qi] = 0.0f;
        #pragma unroll
        for (int dj = 0; dj < 8; dj++) o[qi][dj] = 0.0f;
    }

    const float sc_scale = 0.08838834764831843f;
    const int kend = q0 + BQ;

    for (int k0 = 0; k0 < kend; k0 += BKT) {
        __syncthreads();
        for (int idx = tid; idx < BKT * 32; idx += 256) {
            int r = idx >> 5;
            int c = (idx & 31) * 4;
            *reinterpret_cast<float4*>(&Ks[r * QPAD + c]) =
                *reinterpret_cast<const float4*>(Kg + (size_t)(k0 + r) * DHEAD + c);
            *reinterpret_cast<float4*>(&Vs[r * QPAD + c]) =
                *reinterpret_cast<const float4*>(Vg + (size_t)(k0 + r) * DHEAD + c);
        }
        __syncthreads();

        float sc[4][4];
        #pragma unroll
        for (int qi = 0; qi < 4; qi++)
            #pragma unroll
            for (int ki = 0; ki < 4; ki++) sc[qi][ki] = 0.0f;

        for (int d = 0; d < DHEAD; d += 4) {
            float4 qv[4], kv[4];
            #pragma unroll
            for (int qi = 0; qi < 4; qi++)
                qv[qi] = *reinterpret_cast<float4*>(&Qs[(ty * 4 + qi) * QPAD + d]);
            #pragma unroll
            for (int ki = 0; ki < 4; ki++)
                kv[ki] = *reinterpret_cast<float4*>(&Ks[(tx * 4 + ki) * QPAD + d]);
            #pragma unroll
            for (int qi = 0; qi < 4; qi++)
                #pragma unroll
                for (int ki = 0; ki < 4; ki++) {
                    sc[qi][ki] += qv[qi].x * kv[ki].x;
                    sc[qi][ki] += qv[qi].y * kv[ki].y;
                    sc[qi][ki] += qv[qi].z * kv[ki].z;
                    sc[qi][ki] += qv[qi].w * kv[ki].w;
                }
        }

        #pragma unroll
        for (int qi = 0; qi < 4; qi++) {
            const int qg = q0 + ty * 4 + qi;
            float tmax = -INFINITY;
            #pragma unroll
            for (int ki = 0; ki < 4; ki++) {
                float s = sc[qi][ki] * sc_scale;
                int kg = k0 + tx * 4 + ki;
                if (kg > qg) s = -INFINITY;
                sc[qi][ki] = s;
                tmax = fmaxf(tmax, s);
            }
            #pragma unroll
            for (int off = 8; off > 0; off >>= 1)
                tmax = fmaxf(tmax, __shfl_xor_sync(0xffffffffu, tmax, off));

            float mnew = fmaxf(m[qi], tmax);
            float corr = __expf(m[qi] - mnew);

            float rsum = 0.0f;
            #pragma unroll
            for (int ki = 0; ki < 4; ki++) {
                float p = __expf(sc[qi][ki] - mnew);
                sc[qi][ki] = p;
                rsum += p;
            }
            #pragma unroll
            for (int off = 8; off > 0; off >>= 1)
                rsum += __shfl_xor_sync(0xffffffffu, rsum, off);

            l[qi] = l[qi] * corr + rsum;
            m[qi] = mnew;
            #pragma unroll
            for (int dj = 0; dj < 8; dj++) o[qi][dj] *= corr;

            #pragma unroll
            for (int ki = 0; ki < 4; ki++)
                Ps[(ty * 4 + qi) * PPAD + tx * 4 + ki] = sc[qi][ki];
        }
        __syncthreads();

        for (int kk = 0; kk < BKT; kk++) {
            float4 v0 = *reinterpret_cast<float4*>(&Vs[kk * QPAD + tx * 8]);
            float4 v1 = *reinterpret_cast<float4*>(&Vs[kk * QPAD + tx * 8 + 4]);
            #pragma unroll
            for (int qi = 0; qi < 4; qi++) {
                float p = Ps[(ty * 4 + qi) * PPAD + kk];
                o[qi][0] += p * v0.x; o[qi][1] += p * v0.y;
                o[qi][2] += p * v0.z; o[qi][3] += p * v0.w;
                o[qi][4] += p * v1.x; o[qi][5] += p * v1.y;
                o[qi][6] += p * v1.z; o[qi][7] += p * v1.w;
            }
        }
    }

    #pragma unroll
    for (int qi = 0; qi < 4; qi++) {
        float inv = 1.0f / l[qi];
        int s = q0 + ty * 4 + qi;
        float* zp = g_z + (((size_t)b * SEQ + s) * NHEADS + h) * DHEAD + tx * 8;
        #pragma unroll
        for (int dj = 0; dj < 8; dj++) zp[dj] = o[qi][dj] * inv;
    }
}

// ---------------------------------------------------------------------------
extern "C" void kernel_launch(void* const* d_in, const int* in_sizes, int n_in,
                              void* d_out, int out_size)
{
    (void)in_sizes; (void)n_in; (void)out_size;
    const float* residual = (const float*)d_in[0];
    const float* WQ = (const float*)d_in[2];
    const float* WK = (const float*)d_in[3];
    const float* WV = (const float*)d_in[4];
    const float* WO = (const float*)d_in[5];
    const float* bQ = (const float*)d_in[6];
    const float* bK = (const float*)d_in[7];
    const float* bV = (const float*)d_in[8];
    const float* bO = (const float*)d_in[9];
    float* out = (float*)d_out;

    // tuple element 0: residual pass-through
    cudaMemcpyAsync(out, residual, (size_t)BATCH * SEQ * DMODEL * sizeof(float),
                    cudaMemcpyDeviceToDevice);

    cudaFuncSetAttribute(qkv_tc, cudaFuncAttributeMaxDynamicSharedMemorySize, SM_GEMM);
    cudaFuncSetAttribute(o_tc,   cudaFuncAttributeMaxDynamicSharedMemorySize, SM_GEMM);

    // 1) QKV projection (mma.sync bf16 split)
    dim3 g1(NTOK / 128, NHEADS, 3);
    qkv_tc<<<g1, 256, SM_GEMM>>>(residual, WQ, WK, WV, bQ, bK, bV);

    // 2) causal flash attention (fp32)
    const int attn_smem_bytes = (3 * BKT * QPAD + BQ * PPAD) * (int)sizeof(float);
    cudaFuncSetAttribute(attn_kernel, cudaFuncAttributeMaxDynamicSharedMemorySize,
                         attn_smem_bytes);
    dim3 g2(SEQ / BQ, NHEADS, BATCH);
    attn_kernel<<<g2, 256, attn_smem_bytes>>>();

    // 3) output projection (mma.sync bf16 split)
    dim3 g3(NTOK / 128, DMODEL / 128);
    o_tc<<<g3, 256, SM_GEMM>>>(WO, bO, out + (size_t)BATCH * SEQ * DMODEL);
}

// round 5
// speedup vs baseline: 3.1334x; 1.9405x over previous
#include <cuda_runtime.h>
#include <cuda_bf16.h>
#include <math.h>
#include <stdint.h>

#define BATCH   2
#define SEQ     2048
#define DMODEL  2048
#define NHEADS  16
#define DHEAD   128
#define NTOK    (BATCH * SEQ)      // 4096

// ---------------- scratch (device globals; no allocation allowed) ----------
__device__ float g_q[(size_t)BATCH * NHEADS * SEQ * DHEAD];  // [b][h][s][d]
__device__ float g_k[(size_t)BATCH * NHEADS * SEQ * DHEAD];
__device__ float g_v[(size_t)BATCH * NHEADS * SEQ * DHEAD];
__device__ float g_z[(size_t)BATCH * SEQ * NHEADS * DHEAD];  // [b][s][h][d] == [4096][2048]

// ========================= mma.sync helpers ================================
__device__ __forceinline__ void ldsm_x4(uint32_t r[4], uint32_t addr) {
    asm volatile("ldmatrix.sync.aligned.m8n8.x4.shared.b16 {%0,%1,%2,%3}, [%4];"
                 : "=r"(r[0]), "=r"(r[1]), "=r"(r[2]), "=r"(r[3]) : "r"(addr));
}
__device__ __forceinline__ void ldsm_x4_t(uint32_t r[4], uint32_t addr) {
    asm volatile("ldmatrix.sync.aligned.m8n8.x4.trans.shared.b16 {%0,%1,%2,%3}, [%4];"
                 : "=r"(r[0]), "=r"(r[1]), "=r"(r[2]), "=r"(r[3]) : "r"(addr));
}
__device__ __forceinline__ void mma_bf16(float c[4], const uint32_t a[4],
                                         uint32_t b0, uint32_t b1) {
    asm volatile("mma.sync.aligned.m16n8k16.row.col.f32.bf16.bf16.f32 "
                 "{%0,%1,%2,%3}, {%4,%5,%6,%7}, {%8,%9}, {%0,%1,%2,%3};"
                 : "+f"(c[0]), "+f"(c[1]), "+f"(c[2]), "+f"(c[3])
                 : "r"(a[0]), "r"(a[1]), "r"(a[2]), "r"(a[3]), "r"(b0), "r"(b1));
}
__device__ __forceinline__ uint32_t smem_to_u32(const void* p) {
    uint32_t a;
    asm("{ .reg .u64 t; cvta.to.shared.u64 t, %1; cvt.u32.u64 %0, t; }"
        : "=r"(a) : "l"(p));
    return a;
}
__device__ __forceinline__ uint32_t pack2(__nv_bfloat16 lo, __nv_bfloat16 hi) {
    return (uint32_t)__bfloat16_as_ushort(lo) | ((uint32_t)__bfloat16_as_ushort(hi) << 16);
}
// swizzled byte offset for bf16 element (row m, col c) in a 128-col (256B) row
__device__ __forceinline__ uint32_t swz256(int m, int c) {
    return (uint32_t)(m * 256 + ((((c >> 3) ^ (m & 7))) << 4) + (c & 7) * 2);
}

// ===================== split-bf16 GEMM mainloop (unchanged, R4) ============
#define KT      64
#define SM_AHI  0
#define SM_ALO  16384
#define SM_BHI  32768
#define SM_BLO  49152
#define SM_GEMM 65536

__device__ __forceinline__ void gemm_mainloop(
    const float* __restrict__ A, int lda,
    const float* __restrict__ B, int ldb,
    char* smem, float acc[4][4][4])
{
    const int tid  = threadIdx.x;
    const int lane = tid & 31;
    const int wid  = tid >> 5;
    const int wm   = (wid >> 2) * 64;
    const int wn   = (wid & 3) * 32;
    const uint32_t sb = smem_to_u32(smem);

    for (int k0 = 0; k0 < DMODEL; k0 += KT) {
        __syncthreads();
        #pragma unroll
        for (int it = 0; it < 8; it++) {
            int idx = tid + it * 256;
            int m  = idx >> 4;
            int kq = (idx & 15) * 4;
            float4 v = *reinterpret_cast<const float4*>(A + (size_t)m * lda + k0 + kq);
            __nv_bfloat16 hx = __float2bfloat16(v.x), hy = __float2bfloat16(v.y);
            __nv_bfloat16 hz = __float2bfloat16(v.z), hw = __float2bfloat16(v.w);
            __nv_bfloat16 lx = __float2bfloat16(v.x - __bfloat162float(hx));
            __nv_bfloat16 ly = __float2bfloat16(v.y - __bfloat162float(hy));
            __nv_bfloat16 lz = __float2bfloat16(v.z - __bfloat162float(hz));
            __nv_bfloat16 lw = __float2bfloat16(v.w - __bfloat162float(hw));
            uint32_t off = (uint32_t)(m * 128 + (((kq >> 3) ^ (m & 7)) << 4) + (kq & 7) * 2);
            *reinterpret_cast<uint2*>(smem + SM_AHI + off) = make_uint2(pack2(hx, hy), pack2(hz, hw));
            *reinterpret_cast<uint2*>(smem + SM_ALO + off) = make_uint2(pack2(lx, ly), pack2(lz, lw));
        }
        #pragma unroll
        for (int it = 0; it < 8; it++) {
            int idx = tid + it * 256;
            int k  = idx >> 5;
            int nq = (idx & 31) * 4;
            float4 v = *reinterpret_cast<const float4*>(B + (size_t)(k0 + k) * ldb + nq);
            __nv_bfloat16 hx = __float2bfloat16(v.x), hy = __float2bfloat16(v.y);
            __nv_bfloat16 hz = __float2bfloat16(v.z), hw = __float2bfloat16(v.w);
            __nv_bfloat16 lx = __float2bfloat16(v.x - __bfloat162float(hx));
            __nv_bfloat16 ly = __float2bfloat16(v.y - __bfloat162float(hy));
            __nv_bfloat16 lz = __float2bfloat16(v.z - __bfloat162float(hz));
            __nv_bfloat16 lw = __float2bfloat16(v.w - __bfloat162float(hw));
            uint32_t off = (uint32_t)(k * 256 + (((nq >> 3) ^ (k & 7)) << 4) + (nq & 7) * 2);
            *reinterpret_cast<uint2*>(smem + SM_BHI + off) = make_uint2(pack2(hx, hy), pack2(hz, hw));
            *reinterpret_cast<uint2*>(smem + SM_BLO + off) = make_uint2(pack2(lx, ly), pack2(lz, lw));
        }
        __syncthreads();

        #pragma unroll
        for (int k16 = 0; k16 < 4; k16++) {
            uint32_t bh[4][2], bl[4][2];
            #pragma unroll
            for (int nf = 0; nf < 2; nf++) {
                int kk = k16 * 16 + (lane & 15);
                int nn = wn + nf * 16 + ((lane >> 4) << 3);
                uint32_t off = (uint32_t)(kk * 256 + (((nn >> 3) ^ (kk & 7)) << 4));
                uint32_t r[4];
                ldsm_x4_t(r, sb + SM_BHI + off);
                bh[nf * 2][0] = r[0]; bh[nf * 2][1] = r[1];
                bh[nf * 2 + 1][0] = r[2]; bh[nf * 2 + 1][1] = r[3];
                ldsm_x4_t(r, sb + SM_BLO + off);
                bl[nf * 2][0] = r[0]; bl[nf * 2][1] = r[1];
                bl[nf * 2 + 1][0] = r[2]; bl[nf * 2 + 1][1] = r[3];
            }
            #pragma unroll
            for (int mi = 0; mi < 4; mi++) {
                int mm = wm + mi * 16 + (lane & 15);
                int kk = k16 * 16 + ((lane >> 4) << 3);
                uint32_t off = (uint32_t)(mm * 128 + (((kk >> 3) ^ (mm & 7)) << 4));
                uint32_t ah[4], al[4];
                ldsm_x4(ah, sb + SM_AHI + off);
                ldsm_x4(al, sb + SM_ALO + off);
                #pragma unroll
                for (int ni = 0; ni < 4; ni++) {
                    mma_bf16(acc[mi][ni], ah, bh[ni][0], bh[ni][1]);
                    mma_bf16(acc[mi][ni], ah, bl[ni][0], bl[ni][1]);
                    mma_bf16(acc[mi][ni], al, bh[ni][0], bh[ni][1]);
                }
            }
        }
    }
}

// ----------------------- QKV projection ------------------------------------
__global__ __launch_bounds__(256, 2) void qkv_tc(
    const float* __restrict__ resid,
    const float* __restrict__ WQ, const float* __restrict__ WK,
    const float* __restrict__ WV,
    const float* __restrict__ bQ, const float* __restrict__ bK,
    const float* __restrict__ bV)
{
    extern __shared__ char smem[];
    const int i0 = blockIdx.x * 128;
    const int h  = blockIdx.y;
    const int which = blockIdx.z;

    const float* W    = (which == 0) ? WQ : (which == 1) ? WK : WV;
    const float* bias = (which == 0) ? bQ : (which == 1) ? bK : bV;
    float* outbuf     = (which == 0) ? g_q : (which == 1) ? g_k : g_v;

    float acc[4][4][4];
    #pragma unroll
    for (int mi = 0; mi < 4; mi++)
        #pragma unroll
        for (int ni = 0; ni < 4; ni++)
            #pragma unroll
            for (int j = 0; j < 4; j++) acc[mi][ni][j] = 0.0f;

    gemm_mainloop(resid + (size_t)i0 * DMODEL, DMODEL,
                  W + (size_t)h * DMODEL * DHEAD, DHEAD, smem, acc);

    const int lane = threadIdx.x & 31;
    const int wid  = threadIdx.x >> 5;
    const int wm   = (wid >> 2) * 64;
    const int wn   = (wid & 3) * 32;
    #pragma unroll
    for (int mi = 0; mi < 4; mi++) {
        #pragma unroll
        for (int ni = 0; ni < 4; ni++) {
            int col = wn + ni * 8 + (lane & 3) * 2;
            float b0 = bias[h * DHEAD + col];
            float b1 = bias[h * DHEAD + col + 1];
            #pragma unroll
            for (int half = 0; half < 2; half++) {
                int i = i0 + wm + mi * 16 + (lane >> 2) + half * 8;
                int bb = i >> 11, s = i & 2047;
                float* op = outbuf + (((size_t)bb * NHEADS + h) * SEQ + s) * DHEAD + col;
                float2 v = make_float2(acc[mi][ni][half * 2] + b0,
                                       acc[mi][ni][half * 2 + 1] + b1);
                *reinterpret_cast<float2*>(op) = v;
            }
        }
    }
}

// ----------------------- Output projection ---------------------------------
__global__ __launch_bounds__(256, 2) void o_tc(
    const float* __restrict__ WO, const float* __restrict__ bO,
    float* __restrict__ out)
{
    extern __shared__ char smem[];
    const int i0 = blockIdx.x * 128;
    const int j0 = blockIdx.y * 128;

    float acc[4][4][4];
    #pragma unroll
    for (int mi = 0; mi < 4; mi++)
        #pragma unroll
        for (int ni = 0; ni < 4; ni++)
            #pragma unroll
            for (int j = 0; j < 4; j++) acc[mi][ni][j] = 0.0f;

    gemm_mainloop(g_z + (size_t)i0 * DMODEL, DMODEL, WO + j0, DMODEL, smem, acc);

    const int lane = threadIdx.x & 31;
    const int wid  = threadIdx.x >> 5;
    const int wm   = (wid >> 2) * 64;
    const int wn   = (wid & 3) * 32;
    #pragma unroll
    for (int mi = 0; mi < 4; mi++) {
        #pragma unroll
        for (int ni = 0; ni < 4; ni++) {
            int col = j0 + wn + ni * 8 + (lane & 3) * 2;
            float b0 = bO[col], b1 = bO[col + 1];
            #pragma unroll
            for (int half = 0; half < 2; half++) {
                int i = i0 + wm + mi * 16 + (lane >> 2) + half * 8;
                float2 v = make_float2(acc[mi][ni][half * 2] + b0,
                                       acc[mi][ni][half * 2 + 1] + b1);
                *reinterpret_cast<float2*>(out + (size_t)i * DMODEL + col) = v;
            }
        }
    }
}

// ---------------------------------------------------------------------------
// Causal flash attention on tensor cores (split-bf16, 3-pass both GEMMs).
// BQ=128 rows/CTA, 8 warps x 16 rows; K/V streamed in 64-key tiles.
// ---------------------------------------------------------------------------
#define BQ2 128
#define BK2 64
#define AT_KHI 0
#define AT_KLO 16384
#define AT_VHI 32768
#define AT_VLO 49152
#define AT_QHI 0
#define AT_QLO 32768
#define AT_SMEM 65536

__global__ __launch_bounds__(256, 1) void attn_tc()
{
    extern __shared__ char smem[];
    const uint32_t sb = smem_to_u32(smem);
    const int tid  = threadIdx.x;
    const int lane = tid & 31;
    const int w    = tid >> 5;            // warp 0..7, owns rows w*16..w*16+15
    const int q0   = blockIdx.x * BQ2;
    const int h    = blockIdx.y;
    const int b    = blockIdx.z;

    const float* Qg = g_q + (((size_t)b * NHEADS + h) * SEQ + q0) * DHEAD;
    const float* Kg = g_k + ((size_t)b * NHEADS + h) * SEQ * DHEAD;
    const float* Vg = g_v + ((size_t)b * NHEADS + h) * SEQ * DHEAD;

    // ---- prologue: Q tile [128 x 128] fp32 -> hi/lo bf16 smem -> reg frags
    #pragma unroll
    for (int it = 0; it < 16; it++) {
        int idx = tid + it * 256;                 // 0..4095
        int m  = idx >> 5;                        // 0..127
        int cq = (idx & 31) * 4;                  // 0..124
        float4 v = *reinterpret_cast<const float4*>(Qg + (size_t)m * DHEAD + cq);
        __nv_bfloat16 hx = __float2bfloat16(v.x), hy = __float2bfloat16(v.y);
        __nv_bfloat16 hz = __float2bfloat16(v.z), hw = __float2bfloat16(v.w);
        __nv_bfloat16 lx = __float2bfloat16(v.x - __bfloat162float(hx));
        __nv_bfloat16 ly = __float2bfloat16(v.y - __bfloat162float(hy));
        __nv_bfloat16 lz = __float2bfloat16(v.z - __bfloat162float(hz));
        __nv_bfloat16 lw = __float2bfloat16(v.w - __bfloat162float(hw));
        uint32_t off = swz256(m, cq);
        *reinterpret_cast<uint2*>(smem + AT_QHI + off) = make_uint2(pack2(hx, hy), pack2(hz, hw));
        *reinterpret_cast<uint2*>(smem + AT_QLO + off) = make_uint2(pack2(lx, ly), pack2(lz, lw));
    }
    __syncthreads();

    uint32_t qh[8][4], ql[8][4];
    #pragma unroll
    for (int t = 0; t < 8; t++) {
        int row = w * 16 + (lane & 15);
        int col = t * 16 + ((lane >> 4) << 3);
        uint32_t off = swz256(row, col);
        ldsm_x4(qh[t], sb + AT_QHI + off);
        ldsm_x4(ql[t], sb + AT_QLO + off);
    }
    __syncthreads();   // Q smem now dead; reuse for K/V

    float O[16][4];
    #pragma unroll
    for (int nf = 0; nf < 16; nf++)
        #pragma unroll
        for (int j = 0; j < 4; j++) O[nf][j] = 0.0f;
    float m0 = -INFINITY, m1 = -INFINITY, l0 = 0.0f, l1 = 0.0f;

    const float sc_scale = 0.08838834764831843f;  // 1/sqrt(128)
    const int rbase = q0 + w * 16;
    const int kend = q0 + BQ2;

    for (int k0 = 0; k0 < kend; k0 += BK2) {
        // ---- load K,V tiles [64 x 128] fp32 -> hi/lo bf16 smem
        #pragma unroll
        for (int it = 0; it < 8; it++) {
            int idx = tid + it * 256;             // 0..2047
            int r  = idx >> 5;                    // 0..63
            int cq = (idx & 31) * 4;
            uint32_t off = swz256(r, cq);
            {
                float4 v = *reinterpret_cast<const float4*>(Kg + (size_t)(k0 + r) * DHEAD + cq);
                __nv_bfloat16 hx = __float2bfloat16(v.x), hy = __float2bfloat16(v.y);
                __nv_bfloat16 hz = __float2bfloat16(v.z), hw = __float2bfloat16(v.w);
                __nv_bfloat16 lx = __float2bfloat16(v.x - __bfloat162float(hx));
                __nv_bfloat16 ly = __float2bfloat16(v.y - __bfloat162float(hy));
                __nv_bfloat16 lz = __float2bfloat16(v.z - __bfloat162float(hz));
                __nv_bfloat16 lw = __float2bfloat16(v.w - __bfloat162float(hw));
                *reinterpret_cast<uint2*>(smem + AT_KHI + off) = make_uint2(pack2(hx, hy), pack2(hz, hw));
                *reinterpret_cast<uint2*>(smem + AT_KLO + off) = make_uint2(pack2(lx, ly), pack2(lz, lw));
            }
            {
                float4 v = *reinterpret_cast<const float4*>(Vg + (size_t)(k0 + r) * DHEAD + cq);
                __nv_bfloat16 hx = __float2bfloat16(v.x), hy = __float2bfloat16(v.y);
                __nv_bfloat16 hz = __float2bfloat16(v.z), hw = __float2bfloat16(v.w);
                __nv_bfloat16 lx = __float2bfloat16(v.x - __bfloat162float(hx));
                __nv_bfloat16 ly = __float2bfloat16(v.y - __bfloat162float(hy));
                __nv_bfloat16 lz = __float2bfloat16(v.z - __bfloat162float(hz));
                __nv_bfloat16 lw = __float2bfloat16(v.w - __bfloat162float(hw));
                *reinterpret_cast<uint2*>(smem + AT_VHI + off) = make_uint2(pack2(hx, hy), pack2(hz, hw));
                *reinterpret_cast<uint2*>(smem + AT_VLO + off) = make_uint2(pack2(lx, ly), pack2(lz, lw));
            }
        }
        __syncthreads();

        // ---- S = Q K^T  (split 3-pass), per warp m16 x n64
        float sf[8][4];
        #pragma unroll
        for (int nf = 0; nf < 8; nf++)
            #pragma unroll
            for (int j = 0; j < 4; j++) sf[nf][j] = 0.0f;

        #pragma unroll
        for (int t = 0; t < 8; t++) {
            #pragma unroll
            for (int nb = 0; nb < 4; nb++) {
                int row = nb * 16 + (lane & 15);
                int col = t * 16 + ((lane >> 4) << 3);
                uint32_t off = swz256(row, col);
                uint32_t kh[4], kl[4];
                ldsm_x4(kh, sb + AT_KHI + off);
                ldsm_x4(kl, sb + AT_KLO + off);
                mma_bf16(sf[2 * nb],     qh[t], kh[0], kh[2]);
                mma_bf16(sf[2 * nb],     qh[t], kl[0], kl[2]);
                mma_bf16(sf[2 * nb],     ql[t], kh[0], kh[2]);
                mma_bf16(sf[2 * nb + 1], qh[t], kh[1], kh[3]);
                mma_bf16(sf[2 * nb + 1], qh[t], kl[1], kl[3]);
                mma_bf16(sf[2 * nb + 1], ql[t], kh[1], kh[3]);
            }
        }

        // ---- scale + causal mask (fragment space)
        const bool need_mask = (k0 + BK2 - 1) > (rbase);
        #pragma unroll
        for (int nf = 0; nf < 8; nf++)
            #pragma unroll
            for (int j = 0; j < 4; j++) {
                float s = sf[nf][j] * sc_scale;
                if (need_mask) {
                    int col = k0 + nf * 8 + (lane & 3) * 2 + (j & 1);
                    int row = rbase + (lane >> 2) + (j >> 1) * 8;
                    if (col > row) s = -INFINITY;
                }
                sf[nf][j] = s;
            }

        // ---- online softmax (rows: half0 = lane>>2, half1 = +8)
        float mx0 = -INFINITY, mx1 = -INFINITY;
        #pragma unroll
        for (int nf = 0; nf < 8; nf++) {
            mx0 = fmaxf(mx0, fmaxf(sf[nf][0], sf[nf][1]));
            mx1 = fmaxf(mx1, fmaxf(sf[nf][2], sf[nf][3]));
        }
        mx0 = fmaxf(mx0, __shfl_xor_sync(0xffffffffu, mx0, 1));
        mx0 = fmaxf(mx0, __shfl_xor_sync(0xffffffffu, mx0, 2));
        mx1 = fmaxf(mx1, __shfl_xor_sync(0xffffffffu, mx1, 1));
        mx1 = fmaxf(mx1, __shfl_xor_sync(0xffffffffu, mx1, 2));

        float mn0 = fmaxf(m0, mx0), mn1 = fmaxf(m1, mx1);
        float cr0 = __expf(m0 - mn0), cr1 = __expf(m1 - mn1);

        float sum0 = 0.0f, sum1 = 0.0f;
        #pragma unroll
        for (int nf = 0; nf < 8; nf++) {
            float p0 = __expf(sf[nf][0] - mn0);
            float p1 = __expf(sf[nf][1] - mn0);
            float p2 = __expf(sf[nf][2] - mn1);
            float p3 = __expf(sf[nf][3] - mn1);
            sf[nf][0] = p0; sf[nf][1] = p1; sf[nf][2] = p2; sf[nf][3] = p3;
            sum0 += p0 + p1; sum1 += p2 + p3;
        }
        sum0 += __shfl_xor_sync(0xffffffffu, sum0, 1);
        sum0 += __shfl_xor_sync(0xffffffffu, sum0, 2);
        sum1 += __shfl_xor_sync(0xffffffffu, sum1, 1);
        sum1 += __shfl_xor_sync(0xffffffffu, sum1, 2);
        l0 = l0 * cr0 + sum0;  l1 = l1 * cr1 + sum1;
        m0 = mn0;  m1 = mn1;

        #pragma unroll
        for (int nf = 0; nf < 16; nf++) {
            O[nf][0] *= cr0; O[nf][1] *= cr0;
            O[nf][2] *= cr1; O[nf][3] *= cr1;
        }

        // ---- pack P -> A frags (hi + residual lo)
        uint32_t pa[4][4], pl[4][4];
        #pragma unroll
        for (int kb = 0; kb < 4; kb++) {
            #pragma unroll
            for (int half = 0; half < 2; half++) {     // frag 2kb, 2kb+1
                #pragma unroll
                for (int rr = 0; rr < 2; rr++) {       // regs (0,1) vs (2,3)
                    float f0 = sf[2 * kb + half][rr * 2];
                    float f1 = sf[2 * kb + half][rr * 2 + 1];
                    __nv_bfloat16 h0 = __float2bfloat16(f0), h1 = __float2bfloat16(f1);
                    __nv_bfloat16 e0 = __float2bfloat16(f0 - __bfloat162float(h0));
                    __nv_bfloat16 e1 = __float2bfloat16(f1 - __bfloat162float(h1));
                    pa[kb][half * 2 + rr] = pack2(h0, h1);
                    pl[kb][half * 2 + rr] = pack2(e0, e1);
                }
            }
        }

        // ---- O += P V (split 3-pass), n = 128 d cols
        #pragma unroll
        for (int kb = 0; kb < 4; kb++) {
            #pragma unroll
            for (int nf2 = 0; nf2 < 8; nf2++) {
                int kk = kb * 16 + (lane & 15);
                int nn = nf2 * 16 + ((lane >> 4) << 3);
                uint32_t off = swz256(kk, nn);
                uint32_t vh[4], vl[4];
                ldsm_x4_t(vh, sb + AT_VHI + off);
                ldsm_x4_t(vl, sb + AT_VLO + off);
                mma_bf16(O[2 * nf2],     pa[kb], vh[0], vh[1]);
                mma_bf16(O[2 * nf2],     pa[kb], vl[0], vl[1]);
                mma_bf16(O[2 * nf2],     pl[kb], vh[0], vh[1]);
                mma_bf16(O[2 * nf2 + 1], pa[kb], vh[2], vh[3]);
                mma_bf16(O[2 * nf2 + 1], pa[kb], vl[2], vl[3]);
                mma_bf16(O[2 * nf2 + 1], pl[kb], vh[2], vh[3]);
            }
        }
        __syncthreads();   // all warps done reading K/V before next overwrite
    }

    // ---- normalize + write z [b][s][h][d]
    float inv0 = 1.0f / l0, inv1 = 1.0f / l1;
    int r0 = rbase + (lane >> 2);
    float* z0 = g_z + (((size_t)b * SEQ + r0) * NHEADS + h) * DHEAD;
    float* z1 = g_z + (((size_t)b * SEQ + r0 + 8) * NHEADS + h) * DHEAD;
    #pragma unroll
    for (int nf = 0; nf < 16; nf++) {
        int col = nf * 8 + (lane & 3) * 2;
        *reinterpret_cast<float2*>(z0 + col) = make_float2(O[nf][0] * inv0, O[nf][1] * inv0);
        *reinterpret_cast<float2*>(z1 + col) = make_float2(O[nf][2] * inv1, O[nf][3] * inv1);
    }
}

// ---------------------------------------------------------------------------
extern "C" void kernel_launch(void* const* d_in, const int* in_sizes, int n_in,
                              void* d_out, int out_size)
{
    (void)in_sizes; (void)n_in; (void)out_size;
    const float* residual = (const float*)d_in[0];
    const float* WQ = (const float*)d_in[2];
    const float* WK = (const float*)d_in[3];
    const float* WV = (const float*)d_in[4];
    const float* WO = (const float*)d_in[5];
    const float* bQ = (const float*)d_in[6];
    const float* bK = (const float*)d_in[7];
    const float* bV = (const float*)d_in[8];
    const float* bO = (const float*)d_in[9];
    float* out = (float*)d_out;

    cudaMemcpyAsync(out, residual, (size_t)BATCH * SEQ * DMODEL * sizeof(float),
                    cudaMemcpyDeviceToDevice);

    cudaFuncSetAttribute(qkv_tc,  cudaFuncAttributeMaxDynamicSharedMemorySize, SM_GEMM);
    cudaFuncSetAttribute(o_tc,    cudaFuncAttributeMaxDynamicSharedMemorySize, SM_GEMM);
    cudaFuncSetAttribute(attn_tc, cudaFuncAttributeMaxDynamicSharedMemorySize, AT_SMEM);

    dim3 g1(NTOK / 128, NHEADS, 3);
    qkv_tc<<<g1, 256, SM_GEMM>>>(residual, WQ, WK, WV, bQ, bK, bV);

    dim3 g2(SEQ / BQ2, NHEADS, BATCH);
    attn_tc<<<g2, 256, AT_SMEM>>>();

    dim3 g3(NTOK / 128, DMODEL / 128);
    o_tc<<<g3, 256, SM_GEMM>>>(WO, bO, out + (size_t)BATCH * SEQ * DMODEL);
}

// round 6
// speedup vs baseline: 3.7785x; 1.2059x over previous
#include <cuda_runtime.h>
#include <cuda_bf16.h>
#include <math.h>
#include <stdint.h>

#define BATCH   2
#define SEQ     2048
#define DMODEL  2048
#define NHEADS  16
#define DHEAD   128
#define NTOK    (BATCH * SEQ)      // 4096

typedef __nv_bfloat16 bf16;

// ---------------- scratch (device globals; no allocation allowed) ----------
// split-bf16 copies of inputs
__device__ __align__(16) bf16 g_rhi[(size_t)NTOK * DMODEL];
__device__ __align__(16) bf16 g_rlo[(size_t)NTOK * DMODEL];
__device__ __align__(16) bf16 g_wq_hi[(size_t)NHEADS * DMODEL * DHEAD];
__device__ __align__(16) bf16 g_wq_lo[(size_t)NHEADS * DMODEL * DHEAD];
__device__ __align__(16) bf16 g_wk_hi[(size_t)NHEADS * DMODEL * DHEAD];
__device__ __align__(16) bf16 g_wk_lo[(size_t)NHEADS * DMODEL * DHEAD];
__device__ __align__(16) bf16 g_wv_hi[(size_t)NHEADS * DMODEL * DHEAD];
__device__ __align__(16) bf16 g_wv_lo[(size_t)NHEADS * DMODEL * DHEAD];
__device__ __align__(16) bf16 g_wo_hi[(size_t)DMODEL * DMODEL];
__device__ __align__(16) bf16 g_wo_lo[(size_t)DMODEL * DMODEL];
// split-bf16 activations [b][h][s][d]
__device__ __align__(16) bf16 g_qhi[(size_t)BATCH * NHEADS * SEQ * DHEAD];
__device__ __align__(16) bf16 g_qlo[(size_t)BATCH * NHEADS * SEQ * DHEAD];
__device__ __align__(16) bf16 g_khi[(size_t)BATCH * NHEADS * SEQ * DHEAD];
__device__ __align__(16) bf16 g_klo[(size_t)BATCH * NHEADS * SEQ * DHEAD];
__device__ __align__(16) bf16 g_vhi[(size_t)BATCH * NHEADS * SEQ * DHEAD];
__device__ __align__(16) bf16 g_vlo[(size_t)BATCH * NHEADS * SEQ * DHEAD];
// attention output [b][s][h][d]
__device__ __align__(16) bf16 g_zhi[(size_t)BATCH * SEQ * NHEADS * DHEAD];
__device__ __align__(16) bf16 g_zlo[(size_t)BATCH * SEQ * NHEADS * DHEAD];

// ========================= helpers =========================================
__device__ __forceinline__ void ldsm_x4(uint32_t r[4], uint32_t addr) {
    asm volatile("ldmatrix.sync.aligned.m8n8.x4.shared.b16 {%0,%1,%2,%3}, [%4];"
                 : "=r"(r[0]), "=r"(r[1]), "=r"(r[2]), "=r"(r[3]) : "r"(addr));
}
__device__ __forceinline__ void ldsm_x4_t(uint32_t r[4], uint32_t addr) {
    asm volatile("ldmatrix.sync.aligned.m8n8.x4.trans.shared.b16 {%0,%1,%2,%3}, [%4];"
                 : "=r"(r[0]), "=r"(r[1]), "=r"(r[2]), "=r"(r[3]) : "r"(addr));
}
__device__ __forceinline__ void mma_bf16(float c[4], const uint32_t a[4],
                                         uint32_t b0, uint32_t b1) {
    asm volatile("mma.sync.aligned.m16n8k16.row.col.f32.bf16.bf16.f32 "
                 "{%0,%1,%2,%3}, {%4,%5,%6,%7}, {%8,%9}, {%0,%1,%2,%3};"
                 : "+f"(c[0]), "+f"(c[1]), "+f"(c[2]), "+f"(c[3])
                 : "r"(a[0]), "r"(a[1]), "r"(a[2]), "r"(a[3]), "r"(b0), "r"(b1));
}
__device__ __forceinline__ uint32_t smem_to_u32(const void* p) {
    uint32_t a;
    asm("{ .reg .u64 t; cvta.to.shared.u64 t, %1; cvt.u32.u64 %0, t; }"
        : "=r"(a) : "l"(p));
    return a;
}
__device__ __forceinline__ uint32_t pack2(bf16 lo, bf16 hi) {
    return (uint32_t)__bfloat16_as_ushort(lo) | ((uint32_t)__bfloat16_as_ushort(hi) << 16);
}
__device__ __forceinline__ void cp_async16(uint32_t dst, const void* src) {
    asm volatile("cp.async.cg.shared.global [%0], [%1], 16;" :: "r"(dst), "l"(src));
}
__device__ __forceinline__ void cp_async_commit() {
    asm volatile("cp.async.commit_group;" ::: "memory");
}
__device__ __forceinline__ void cp_async_wait0() {
    asm volatile("cp.async.wait_group 0;" ::: "memory");
}
__device__ __forceinline__ void split2(float f, bf16& h, bf16& l) {
    h = __float2bfloat16(f);
    l = __float2bfloat16(f - __bfloat162float(h));
}

// ===================== conversion pre-pass =================================
__global__ __launch_bounds__(256) void convert_split(
    const float* __restrict__ src, bf16* __restrict__ hi, bf16* __restrict__ lo,
    int n4)
{
    int i = blockIdx.x * 256 + threadIdx.x;
    if (i >= n4) return;
    float4 v = reinterpret_cast<const float4*>(src)[i];
    bf16 hx, hy, hz, hw, lx, ly, lz, lw;
    split2(v.x, hx, lx); split2(v.y, hy, ly);
    split2(v.z, hz, lz); split2(v.w, hw, lw);
    reinterpret_cast<uint2*>(hi)[i] = make_uint2(pack2(hx, hy), pack2(hz, hw));
    reinterpret_cast<uint2*>(lo)[i] = make_uint2(pack2(lx, ly), pack2(lz, lw));
}

// ===================== split-bf16 GEMM mainloop (cp.async) =================
#define KT      64
#define SM_AHI  0
#define SM_ALO  16384
#define SM_BHI  32768
#define SM_BLO  49152
#define SM_GEMM 65536

__device__ __forceinline__ void gemm_mainloop_bf16(
    const bf16* __restrict__ Ahi, const bf16* __restrict__ Alo, int lda,
    const bf16* __restrict__ Bhi, const bf16* __restrict__ Blo, int ldb,
    char* smem, float acc[4][4][4])
{
    const int tid  = threadIdx.x;
    const int lane = tid & 31;
    const int wid  = tid >> 5;
    const int wm   = (wid >> 2) * 64;
    const int wn   = (wid & 3) * 32;
    const uint32_t sb = smem_to_u32(smem);

    for (int k0 = 0; k0 < DMODEL; k0 += KT) {
        __syncthreads();
        // A tiles: 128 rows x 64 cols bf16 (128B rows), 1024 x 16B chunks each
        #pragma unroll
        for (int it = 0; it < 4; it++) {
            int idx = tid + it * 256;
            int m  = idx >> 3;
            int c8 = idx & 7;
            uint32_t d = (uint32_t)(m * 128 + ((c8 ^ (m & 7)) << 4));
            size_t so = (size_t)m * lda + k0 + c8 * 8;
            cp_async16(sb + SM_AHI + d, Ahi + so);
            cp_async16(sb + SM_ALO + d, Alo + so);
        }
        // B tiles: 64 rows x 128 cols bf16 (256B rows)
        #pragma unroll
        for (int it = 0; it < 4; it++) {
            int idx = tid + it * 256;
            int k  = idx >> 4;
            int c8 = idx & 15;
            uint32_t d = (uint32_t)(k * 256 + ((c8 ^ (k & 7)) << 4));
            size_t so = (size_t)(k0 + k) * ldb + c8 * 8;
            cp_async16(sb + SM_BHI + d, Bhi + so);
            cp_async16(sb + SM_BLO + d, Blo + so);
        }
        cp_async_commit();
        cp_async_wait0();
        __syncthreads();

        #pragma unroll
        for (int k16 = 0; k16 < 4; k16++) {
            uint32_t bh[4][2], bl[4][2];
            #pragma unroll
            for (int nf = 0; nf < 2; nf++) {
                int kk = k16 * 16 + (lane & 15);
                int nn = wn + nf * 16 + ((lane >> 4) << 3);
                uint32_t off = (uint32_t)(kk * 256 + (((nn >> 3) ^ (kk & 7)) << 4));
                uint32_t r[4];
                ldsm_x4_t(r, sb + SM_BHI + off);
                bh[nf * 2][0] = r[0]; bh[nf * 2][1] = r[1];
                bh[nf * 2 + 1][0] = r[2]; bh[nf * 2 + 1][1] = r[3];
                ldsm_x4_t(r, sb + SM_BLO + off);
                bl[nf * 2][0] = r[0]; bl[nf * 2][1] = r[1];
                bl[nf * 2 + 1][0] = r[2]; bl[nf * 2 + 1][1] = r[3];
            }
            #pragma unroll
            for (int mi = 0; mi < 4; mi++) {
                int mm = wm + mi * 16 + (lane & 15);
                int kk = k16 * 16 + ((lane >> 4) << 3);
                uint32_t off = (uint32_t)(mm * 128 + (((kk >> 3) ^ (mm & 7)) << 4));
                uint32_t ah[4], al[4];
                ldsm_x4(ah, sb + SM_AHI + off);
                ldsm_x4(al, sb + SM_ALO + off);
                #pragma unroll
                for (int ni = 0; ni < 4; ni++) {
                    mma_bf16(acc[mi][ni], ah, bh[ni][0], bh[ni][1]);
                    mma_bf16(acc[mi][ni], ah, bl[ni][0], bl[ni][1]);
                    mma_bf16(acc[mi][ni], al, bh[ni][0], bh[ni][1]);
                }
            }
        }
    }
}

// ----------------------- QKV projection ------------------------------------
__global__ __launch_bounds__(256, 2) void qkv_tc(
    const float* __restrict__ bQ, const float* __restrict__ bK,
    const float* __restrict__ bV)
{
    extern __shared__ char smem[];
    const int i0 = blockIdx.x * 128;
    const int h  = blockIdx.y;
    const int which = blockIdx.z;

    const bf16* Whi = (which == 0) ? g_wq_hi : (which == 1) ? g_wk_hi : g_wv_hi;
    const bf16* Wlo = (which == 0) ? g_wq_lo : (which == 1) ? g_wk_lo : g_wv_lo;
    const float* bias = (which == 0) ? bQ : (which == 1) ? bK : bV;
    bf16* ohi = (which == 0) ? g_qhi : (which == 1) ? g_khi : g_vhi;
    bf16* olo = (which == 0) ? g_qlo : (which == 1) ? g_klo : g_vlo;

    float acc[4][4][4];
    #pragma unroll
    for (int mi = 0; mi < 4; mi++)
        #pragma unroll
        for (int ni = 0; ni < 4; ni++)
            #pragma unroll
            for (int j = 0; j < 4; j++) acc[mi][ni][j] = 0.0f;

    gemm_mainloop_bf16(g_rhi + (size_t)i0 * DMODEL, g_rlo + (size_t)i0 * DMODEL, DMODEL,
                       Whi + (size_t)h * DMODEL * DHEAD, Wlo + (size_t)h * DMODEL * DHEAD,
                       DHEAD, smem, acc);

    const int lane = threadIdx.x & 31;
    const int wid  = threadIdx.x >> 5;
    const int wm   = (wid >> 2) * 64;
    const int wn   = (wid & 3) * 32;
    #pragma unroll
    for (int mi = 0; mi < 4; mi++) {
        #pragma unroll
        for (int ni = 0; ni < 4; ni++) {
            int col = wn + ni * 8 + (lane & 3) * 2;
            float b0 = bias[h * DHEAD + col];
            float b1 = bias[h * DHEAD + col + 1];
            #pragma unroll
            for (int half = 0; half < 2; half++) {
                int i = i0 + wm + mi * 16 + (lane >> 2) + half * 8;
                int bb = i >> 11, s = i & 2047;
                size_t base = (((size_t)bb * NHEADS + h) * SEQ + s) * DHEAD + col;
                float f0 = acc[mi][ni][half * 2] + b0;
                float f1 = acc[mi][ni][half * 2 + 1] + b1;
                bf16 h0, h1, l0, l1;
                split2(f0, h0, l0); split2(f1, h1, l1);
                *reinterpret_cast<uint32_t*>(&ohi[base]) = pack2(h0, h1);
                *reinterpret_cast<uint32_t*>(&olo[base]) = pack2(l0, l1);
            }
        }
    }
}

// ----------------------- Output projection ---------------------------------
__global__ __launch_bounds__(256, 2) void o_tc(
    const float* __restrict__ bO, float* __restrict__ out)
{
    extern __shared__ char smem[];
    const int i0 = blockIdx.x * 128;
    const int j0 = blockIdx.y * 128;

    float acc[4][4][4];
    #pragma unroll
    for (int mi = 0; mi < 4; mi++)
        #pragma unroll
        for (int ni = 0; ni < 4; ni++)
            #pragma unroll
            for (int j = 0; j < 4; j++) acc[mi][ni][j] = 0.0f;

    gemm_mainloop_bf16(g_zhi + (size_t)i0 * DMODEL, g_zlo + (size_t)i0 * DMODEL, DMODEL,
                       g_wo_hi + j0, g_wo_lo + j0, DMODEL, smem, acc);

    const int lane = threadIdx.x & 31;
    const int wid  = threadIdx.x >> 5;
    const int wm   = (wid >> 2) * 64;
    const int wn   = (wid & 3) * 32;
    #pragma unroll
    for (int mi = 0; mi < 4; mi++) {
        #pragma unroll
        for (int ni = 0; ni < 4; ni++) {
            int col = j0 + wn + ni * 8 + (lane & 3) * 2;
            float b0 = bO[col], b1 = bO[col + 1];
            #pragma unroll
            for (int half = 0; half < 2; half++) {
                int i = i0 + wm + mi * 16 + (lane >> 2) + half * 8;
                float2 v = make_float2(acc[mi][ni][half * 2] + b0,
                                       acc[mi][ni][half * 2 + 1] + b1);
                *reinterpret_cast<float2*>(out + (size_t)i * DMODEL + col) = v;
            }
        }
    }
}

// ---------------------------------------------------------------------------
// Causal flash attention, tensor cores, all-bf16-hi/lo operands via cp.async.
// ---------------------------------------------------------------------------
#define BQ2 128
#define BK2 64
#define AT_KHI 0
#define AT_KLO 16384
#define AT_VHI 32768
#define AT_VLO 49152
#define AT_QHI 0
#define AT_QLO 32768
#define AT_SMEM 65536

__global__ __launch_bounds__(256, 1) void attn_tc()
{
    extern __shared__ char smem[];
    const uint32_t sb = smem_to_u32(smem);
    const int tid  = threadIdx.x;
    const int lane = tid & 31;
    const int w    = tid >> 5;
    const int q0   = blockIdx.x * BQ2;
    const int h    = blockIdx.y;
    const int b    = blockIdx.z;

    const size_t head_off = ((size_t)b * NHEADS + h) * SEQ * DHEAD;
    const bf16* Qhig = g_qhi + head_off + (size_t)q0 * DHEAD;
    const bf16* Qlog = g_qlo + head_off + (size_t)q0 * DHEAD;
    const bf16* Khig = g_khi + head_off;
    const bf16* Klog = g_klo + head_off;
    const bf16* Vhig = g_vhi + head_off;
    const bf16* Vlog = g_vlo + head_off;

    // ---- Q prologue: cp.async [128 x 128] hi/lo, then ldsm to frags
    #pragma unroll
    for (int it = 0; it < 8; it++) {
        int idx = tid + it * 256;               // 0..2047
        int m  = idx >> 4;
        int c8 = idx & 15;
        uint32_t d = (uint32_t)(m * 256 + ((c8 ^ (m & 7)) << 4));
        size_t so = (size_t)m * DHEAD + c8 * 8;
        cp_async16(sb + AT_QHI + d, Qhig + so);
        cp_async16(sb + AT_QLO + d, Qlog + so);
    }
    cp_async_commit();
    cp_async_wait0();
    __syncthreads();

    uint32_t qh[8][4], ql[8][4];
    #pragma unroll
    for (int t = 0; t < 8; t++) {
        int row = w * 16 + (lane & 15);
        int col = t * 16 + ((lane >> 4) << 3);
        uint32_t off = (uint32_t)(row * 256 + (((col >> 3) ^ (row & 7)) << 4));
        ldsm_x4(qh[t], sb + AT_QHI + off);
        ldsm_x4(ql[t], sb + AT_QLO + off);
    }
    __syncthreads();   // Q smem dead; reuse for K/V

    float O[16][4];
    #pragma unroll
    for (int nf = 0; nf < 16; nf++)
        #pragma unroll
        for (int j = 0; j < 4; j++) O[nf][j] = 0.0f;
    float m0 = -INFINITY, m1 = -INFINITY, l0 = 0.0f, l1 = 0.0f;

    const float sc_scale = 0.08838834764831843f;
    const int rbase = q0 + w * 16;
    const int kend = q0 + BQ2;

    for (int k0 = 0; k0 < kend; k0 += BK2) {
        // ---- K/V tiles via cp.async (64 x 128 bf16 each, hi+lo)
        #pragma unroll
        for (int it = 0; it < 4; it++) {
            int idx = tid + it * 256;           // 0..1023
            int r  = idx >> 4;
            int c8 = idx & 15;
            uint32_t d = (uint32_t)(r * 256 + ((c8 ^ (r & 7)) << 4));
            size_t so = (size_t)(k0 + r) * DHEAD + c8 * 8;
            cp_async16(sb + AT_KHI + d, Khig + so);
            cp_async16(sb + AT_KLO + d, Klog + so);
            cp_async16(sb + AT_VHI + d, Vhig + so);
            cp_async16(sb + AT_VLO + d, Vlog + so);
        }
        cp_async_commit();
        cp_async_wait0();
        __syncthreads();

        // ---- S = Q K^T (3-pass split)
        float sf[8][4];
        #pragma unroll
        for (int nf = 0; nf < 8; nf++)
            #pragma unroll
            for (int j = 0; j < 4; j++) sf[nf][j] = 0.0f;

        #pragma unroll
        for (int t = 0; t < 8; t++) {
            #pragma unroll
            for (int nb = 0; nb < 4; nb++) {
                int row = nb * 16 + (lane & 15);
                int col = t * 16 + ((lane >> 4) << 3);
                uint32_t off = (uint32_t)(row * 256 + (((col >> 3) ^ (row & 7)) << 4));
                uint32_t kh[4], kl[4];
                ldsm_x4(kh, sb + AT_KHI + off);
                ldsm_x4(kl, sb + AT_KLO + off);
                mma_bf16(sf[2 * nb],     qh[t], kh[0], kh[2]);
                mma_bf16(sf[2 * nb],     qh[t], kl[0], kl[2]);
                mma_bf16(sf[2 * nb],     ql[t], kh[0], kh[2]);
                mma_bf16(sf[2 * nb + 1], qh[t], kh[1], kh[3]);
                mma_bf16(sf[2 * nb + 1], qh[t], kl[1], kl[3]);
                mma_bf16(sf[2 * nb + 1], ql[t], kh[1], kh[3]);
            }
        }

        // ---- scale + causal mask
        const bool need_mask = (k0 + BK2 - 1) > (rbase);
        #pragma unroll
        for (int nf = 0; nf < 8; nf++)
            #pragma unroll
            for (int j = 0; j < 4; j++) {
                float s = sf[nf][j] * sc_scale;
                if (need_mask) {
                    int col = k0 + nf * 8 + (lane & 3) * 2 + (j & 1);
                    int row = rbase + (lane >> 2) + (j >> 1) * 8;
                    if (col > row) s = -INFINITY;
                }
                sf[nf][j] = s;
            }

        // ---- online softmax
        float mx0 = -INFINITY, mx1 = -INFINITY;
        #pragma unroll
        for (int nf = 0; nf < 8; nf++) {
            mx0 = fmaxf(mx0, fmaxf(sf[nf][0], sf[nf][1]));
            mx1 = fmaxf(mx1, fmaxf(sf[nf][2], sf[nf][3]));
        }
        mx0 = fmaxf(mx0, __shfl_xor_sync(0xffffffffu, mx0, 1));
        mx0 = fmaxf(mx0, __shfl_xor_sync(0xffffffffu, mx0, 2));
        mx1 = fmaxf(mx1, __shfl_xor_sync(0xffffffffu, mx1, 1));
        mx1 = fmaxf(mx1, __shfl_xor_sync(0xffffffffu, mx1, 2));

        float mn0 = fmaxf(m0, mx0), mn1 = fmaxf(m1, mx1);
        float cr0 = __expf(m0 - mn0), cr1 = __expf(m1 - mn1);

        float sum0 = 0.0f, sum1 = 0.0f;
        #pragma unroll
        for (int nf = 0; nf < 8; nf++) {
            float p0 = __expf(sf[nf][0] - mn0);
            float p1 = __expf(sf[nf][1] - mn0);
            float p2 = __expf(sf[nf][2] - mn1);
            float p3 = __expf(sf[nf][3] - mn1);
            sf[nf][0] = p0; sf[nf][1] = p1; sf[nf][2] = p2; sf[nf][3] = p3;
            sum0 += p0 + p1; sum1 += p2 + p3;
        }
        sum0 += __shfl_xor_sync(0xffffffffu, sum0, 1);
        sum0 += __shfl_xor_sync(0xffffffffu, sum0, 2);
        sum1 += __shfl_xor_sync(0xffffffffu, sum1, 1);
        sum1 += __shfl_xor_sync(0xffffffffu, sum1, 2);
        l0 = l0 * cr0 + sum0;  l1 = l1 * cr1 + sum1;
        m0 = mn0;  m1 = mn1;

        #pragma unroll
        for (int nf = 0; nf < 16; nf++) {
            O[nf][0] *= cr0; O[nf][1] *= cr0;
            O[nf][2] *= cr1; O[nf][3] *= cr1;
        }

        // ---- P -> A frags (hi + residual lo)
        uint32_t pa[4][4], pl[4][4];
        #pragma unroll
        for (int kb = 0; kb < 4; kb++) {
            #pragma unroll
            for (int half = 0; half < 2; half++) {
                #pragma unroll
                for (int rr = 0; rr < 2; rr++) {
                    float f0 = sf[2 * kb + half][rr * 2];
                    float f1 = sf[2 * kb + half][rr * 2 + 1];
                    bf16 h0, h1, e0, e1;
                    split2(f0, h0, e0); split2(f1, h1, e1);
                    pa[kb][half * 2 + rr] = pack2(h0, h1);
                    pl[kb][half * 2 + rr] = pack2(e0, e1);
                }
            }
        }

        // ---- O += P V (3-pass split)
        #pragma unroll
        for (int kb = 0; kb < 4; kb++) {
            #pragma unroll
            for (int nf2 = 0; nf2 < 8; nf2++) {
                int kk = kb * 16 + (lane & 15);
                int nn = nf2 * 16 + ((lane >> 4) << 3);
                uint32_t off = (uint32_t)(kk * 256 + (((nn >> 3) ^ (kk & 7)) << 4));
                uint32_t vh[4], vl[4];
                ldsm_x4_t(vh, sb + AT_VHI + off);
                ldsm_x4_t(vl, sb + AT_VLO + off);
                mma_bf16(O[2 * nf2],     pa[kb], vh[0], vh[1]);
                mma_bf16(O[2 * nf2],     pa[kb], vl[0], vl[1]);
                mma_bf16(O[2 * nf2],     pl[kb], vh[0], vh[1]);
                mma_bf16(O[2 * nf2 + 1], pa[kb], vh[2], vh[3]);
                mma_bf16(O[2 * nf2 + 1], pa[kb], vl[2], vl[3]);
                mma_bf16(O[2 * nf2 + 1], pl[kb], vh[2], vh[3]);
            }
        }
        __syncthreads();
    }

    // ---- normalize + write z (split hi/lo bf16) [b][s][h][d]
    float inv0 = 1.0f / l0, inv1 = 1.0f / l1;
    int r0 = rbase + (lane >> 2);
    size_t z0 = (((size_t)b * SEQ + r0) * NHEADS + h) * DHEAD;
    size_t z1 = (((size_t)b * SEQ + r0 + 8) * NHEADS + h) * DHEAD;
    #pragma unroll
    for (int nf = 0; nf < 16; nf++) {
        int col = nf * 8 + (lane & 3) * 2;
        bf16 h0, h1, e0, e1;
        split2(O[nf][0] * inv0, h0, e0);
        split2(O[nf][1] * inv0, h1, e1);
        *reinterpret_cast<uint32_t*>(&g_zhi[z0 + col]) = pack2(h0, h1);
        *reinterpret_cast<uint32_t*>(&g_zlo[z0 + col]) = pack2(e0, e1);
        split2(O[nf][2] * inv1, h0, e0);
        split2(O[nf][3] * inv1, h1, e1);
        *reinterpret_cast<uint32_t*>(&g_zhi[z1 + col]) = pack2(h0, h1);
        *reinterpret_cast<uint32_t*>(&g_zlo[z1 + col]) = pack2(e0, e1);
    }
}

// ---------------------------------------------------------------------------
extern "C" void kernel_launch(void* const* d_in, const int* in_sizes, int n_in,
                              void* d_out, int out_size)
{
    (void)in_sizes; (void)n_in; (void)out_size;
    const float* residual = (const float*)d_in[0];
    const float* WQ = (const float*)d_in[2];
    const float* WK = (const float*)d_in[3];
    const float* WV = (const float*)d_in[4];
    const float* WO = (const float*)d_in[5];
    const float* bQ = (const float*)d_in[6];
    const float* bK = (const float*)d_in[7];
    const float* bV = (const float*)d_in[8];
    const float* bO = (const float*)d_in[9];
    float* out = (float*)d_out;

    // tuple element 0: residual pass-through
    cudaMemcpyAsync(out, residual, (size_t)BATCH * SEQ * DMODEL * sizeof(float),
                    cudaMemcpyDeviceToDevice);

    // resolve device-global addresses for the convert pre-pass
    bf16 *rhi, *rlo, *wqh, *wql, *wkh, *wkl, *wvh, *wvl, *woh, *wol;
    cudaGetSymbolAddress((void**)&rhi, g_rhi);  cudaGetSymbolAddress((void**)&rlo, g_rlo);
    cudaGetSymbolAddress((void**)&wqh, g_wq_hi); cudaGetSymbolAddress((void**)&wql, g_wq_lo);
    cudaGetSymbolAddress((void**)&wkh, g_wk_hi); cudaGetSymbolAddress((void**)&wkl, g_wk_lo);
    cudaGetSymbolAddress((void**)&wvh, g_wv_hi); cudaGetSymbolAddress((void**)&wvl, g_wv_lo);
    cudaGetSymbolAddress((void**)&woh, g_wo_hi); cudaGetSymbolAddress((void**)&wol, g_wo_lo);

    const int nR = NTOK * DMODEL / 4;                 // 2.09M float4
    const int nW = NHEADS * DMODEL * DHEAD / 4;       // 1.05M float4
    convert_split<<<(nR + 255) / 256, 256>>>(residual, rhi, rlo, nR);
    convert_split<<<(nW + 255) / 256, 256>>>(WQ, wqh, wql, nW);
    convert_split<<<(nW + 255) / 256, 256>>>(WK, wkh, wkl, nW);
    convert_split<<<(nW + 255) / 256, 256>>>(WV, wvh, wvl, nW);
    convert_split<<<(nW + 255) / 256, 256>>>(WO, woh, wol, nW);

    cudaFuncSetAttribute(qkv_tc,  cudaFuncAttributeMaxDynamicSharedMemorySize, SM_GEMM);
    cudaFuncSetAttribute(o_tc,    cudaFuncAttributeMaxDynamicSharedMemorySize, SM_GEMM);
    cudaFuncSetAttribute(attn_tc, cudaFuncAttributeMaxDynamicSharedMemorySize, AT_SMEM);

    dim3 g1(NTOK / 128, NHEADS, 3);
    qkv_tc<<<g1, 256, SM_GEMM>>>(bQ, bK, bV);

    dim3 g2(SEQ / BQ2, NHEADS, BATCH);
    attn_tc<<<g2, 256, AT_SMEM>>>();

    dim3 g3(NTOK / 128, DMODEL / 128);
    o_tc<<<g3, 256, SM_GEMM>>>(bO, out + (size_t)BATCH * SEQ * DMODEL);
}